// round 1
// baseline (speedup 1.0000x reference)
#include <cuda_runtime.h>
#include <math.h>

#define BATCH 8
#define NA 147456
#define PRE 2000
#define POST 300
#define CAP 4096
#define NBIN 4096
#define SLOTS 2048
#define NMS_THR 0.7f
#define IMG 1024.0f
#define ABASE 16.0f

// ---------------- scratch ----------------
__device__ unsigned int       g_hist[BATCH][NBIN];
__device__ int                g_thresh[BATCH];
__device__ int                g_count[BATCH];
__device__ unsigned long long g_ckey[BATCH][CAP];
__device__ float4             g_cbox[BATCH][CAP];
__device__ float              g_cscore[BATCH][CAP];
__device__ float              g_by1[BATCH][SLOTS], g_bx1[BATCH][SLOTS];
__device__ float              g_by2[BATCH][SLOTS], g_bx2[BATCH][SLOTS];
__device__ float              g_sscore[BATCH][SLOTS];
__device__ int                g_K[BATCH];
__device__ unsigned long long g_mask[BATCH][PRE][32];

// ---------------- decode ----------------
__device__ __forceinline__ void decode_box(float4 a, float4 r,
                                           float4& box, bool& valid) {
    float ah  = a.z - a.x;
    float aw  = a.w - a.y;
    float acy = a.x + 0.5f * ah;
    float acx = a.y + 0.5f * aw;
    float cy  = r.x * ah + acy;
    float cx  = r.y * aw + acx;
    float hh  = (float)exp((double)r.z) * ah;
    float ww  = (float)exp((double)r.w) * aw;
    float y1 = fminf(fmaxf(cy - 0.5f * hh, 0.0f), IMG);
    float x1 = fminf(fmaxf(cx - 0.5f * ww, 0.0f), IMG);
    float y2 = fminf(fmaxf(cy + 0.5f * hh, 0.0f), IMG);
    float x2 = fminf(fmaxf(cx + 0.5f * ww, 0.0f), IMG);
    box = make_float4(y1, x1, y2, x2);
    valid = ((y2 - y1) >= ABASE) && ((x2 - x1) >= ABASE);
}

__device__ __forceinline__ int score_bin(float s) {
    int b = (int)(s * 4096.0f);
    return b > 4095 ? 4095 : (b < 0 ? 0 : b);
}

// ---------------- K0: init outputs + scratch ----------------
__global__ void k_init(float* out) {
    int t = blockIdx.x * blockDim.x + threadIdx.x;
    if (t < BATCH * POST * 5) out[t] = 0.0f;                 // boxes+scores
    if (t < BATCH * POST) out[BATCH * POST * 5 + t] = (float)(t / POST); // indices
    if (t < BATCH * NBIN) ((unsigned int*)g_hist)[t] = 0u;
    if (t < BATCH) g_count[t] = 0;
}

// ---------------- K1: histogram ----------------
__global__ void k_hist(const float* __restrict__ anchor,
                       const float* __restrict__ reg,
                       const float* __restrict__ score) {
    __shared__ unsigned int sh[NBIN];
    int b = blockIdx.y;
    for (int i = threadIdx.x; i < NBIN; i += 256) sh[i] = 0;
    __syncthreads();
    const float4* A = (const float4*)anchor + (size_t)b * NA;
    const float4* R = (const float4*)reg + (size_t)b * NA;
    const float*  S = score + (size_t)b * NA;
    int base = blockIdx.x * 1024;
#pragma unroll
    for (int k = 0; k < 4; k++) {
        int i = base + k * 256 + threadIdx.x;   // 144*1024 == NA exactly
        float4 box; bool valid;
        decode_box(A[i], R[i], box, valid);
        if (valid) atomicAdd(&sh[score_bin(S[i])], 1u);
    }
    __syncthreads();
    for (int i = threadIdx.x; i < NBIN; i += 256)
        if (sh[i]) atomicAdd(&g_hist[b][i], sh[i]);
}

// ---------------- K2: threshold bin per batch ----------------
__global__ void k_thresh() {
    int b = threadIdx.x;
    if (b >= BATCH) return;
    unsigned int acc = 0;
    int t = 0;
    for (int bin = NBIN - 1; bin >= 0; --bin) {
        acc += g_hist[b][bin];
        if (acc >= PRE) { t = bin; break; }
    }
    g_thresh[b] = t;
}

// ---------------- K3: gather candidates ----------------
__global__ void k_gather(const float* __restrict__ anchor,
                         const float* __restrict__ reg,
                         const float* __restrict__ score) {
    int b = blockIdx.y;
    int i = blockIdx.x * 256 + threadIdx.x;   // 576*256 == NA exactly
    const float4* A = (const float4*)anchor + (size_t)b * NA;
    const float4* R = (const float4*)reg + (size_t)b * NA;
    float s = score[(size_t)b * NA + i];
    float4 box; bool valid;
    decode_box(A[i], R[i], box, valid);
    bool cand = valid && (score_bin(s) >= g_thresh[b]);
    unsigned ballot = __ballot_sync(0xffffffffu, cand);
    if (cand) {
        int lane = threadIdx.x & 31;
        int leader = __ffs(ballot) - 1;
        int rank = __popc(ballot & ((1u << lane) - 1u));
        int pos = 0;
        if (lane == leader) pos = atomicAdd(&g_count[b], __popc(ballot));
        pos = __shfl_sync(ballot, pos, leader) + rank;
        if (pos < CAP) {
            unsigned u = __float_as_uint(s) | 0x80000000u;   // s >= 0
            g_ckey[b][pos] = ((unsigned long long)u << 32) | (unsigned)(~i);
            g_cbox[b][pos] = box;
            g_cscore[b][pos] = s;
        }
    }
}

// ---------------- K4: per-batch bitonic sort (descending) ----------------
__global__ void k_sort() {
    __shared__ unsigned long long kk[CAP];
    __shared__ unsigned short    pp[CAP];
    int b = blockIdx.x;
    int C = g_count[b];
    if (C > CAP) C = CAP;
    for (int i = threadIdx.x; i < CAP; i += 1024) {
        kk[i] = (i < C) ? g_ckey[b][i] : 0ULL;   // real keys have top bit set
        pp[i] = (unsigned short)i;
    }
    __syncthreads();
    for (int k = 2; k <= CAP; k <<= 1) {
        for (int j = k >> 1; j > 0; j >>= 1) {
#pragma unroll
            for (int e = 0; e < 4; e++) {
                int i = threadIdx.x + e * 1024;
                int ixj = i ^ j;
                if (ixj > i) {
                    unsigned long long a = kk[i], c = kk[ixj];
                    bool descBlk = ((i & k) == 0);
                    bool sw = descBlk ? (a < c) : (a > c);
                    if (sw) {
                        kk[i] = c; kk[ixj] = a;
                        unsigned short t = pp[i]; pp[i] = pp[ixj]; pp[ixj] = t;
                    }
                }
            }
            __syncthreads();
        }
    }
    int Kb = (C < PRE) ? C : PRE;
    if (threadIdx.x == 0) g_K[b] = Kb;
    for (int p = threadIdx.x; p < SLOTS; p += 1024) {
        float4 bx = make_float4(0.f, 0.f, 0.f, 0.f);
        float sc = 0.f;
        if (p < Kb) {
            int slot = pp[p];
            bx = g_cbox[b][slot];
            sc = g_cscore[b][slot];
        }
        g_by1[b][p] = bx.x; g_bx1[b][p] = bx.y;
        g_by2[b][p] = bx.z; g_bx2[b][p] = bx.w;
        g_sscore[b][p] = sc;
    }
}

// ---------------- K5: suppression bitmask ----------------
__global__ void k_mask() {
    __shared__ float sy1[SLOTS], sx1[SLOTS], sy2[SLOTS], sx2[SLOTS];
    int b = blockIdx.y;
    int tile = blockIdx.x;
    for (int j = threadIdx.x; j < SLOTS; j += 256) {
        sy1[j] = g_by1[b][j]; sx1[j] = g_bx1[b][j];
        sy2[j] = g_by2[b][j]; sx2[j] = g_bx2[b][j];
    }
    __syncthreads();
    int lane = threadIdx.x & 31;
    int w = lane;
#pragma unroll
    for (int p = 0; p < 8; p++) {
        int il = (threadIdx.x >> 5) + p * 8;
        int i = tile * 64 + il;            // warp-uniform
        if (i >= PRE) break;
        float iy1 = sy1[i], ix1 = sx1[i], iy2 = sy2[i], ix2 = sx2[i];
        float ia = (iy2 - iy1) * (ix2 - ix1);
        unsigned long long bits = 0ULL;
        for (int kk = 0; kk < 64; kk++) {
            int k2 = (kk + lane) & 63;      // stagger: conflict-free smem
            int j = w * 64 + k2;
            if (j > i) {
                float jy1 = sy1[j], jx1 = sx1[j], jy2 = sy2[j], jx2 = sx2[j];
                float ty = fmaxf(iy1, jy1);
                float by = fminf(iy2, jy2);
                float lx = fmaxf(ix1, jx1);
                float rx = fminf(ix2, jx2);
                float inter = fmaxf(by - ty, 0.f) * fmaxf(rx - lx, 0.f);
                float ja = (jy2 - jy1) * (jx2 - jx1);
                float iou = inter / (ia + ja - inter + 1e-9f);
                if (iou > NMS_THR) bits |= (1ULL << k2);
            }
        }
        g_mask[b][i][w] = bits;
    }
}

// ---------------- K6: sequential greedy scan + compaction ----------------
__global__ void k_scan(float* out) {
    int b = blockIdx.x;
    int lane = threadIdx.x;   // 32 threads
    int Kb = g_K[b];

    unsigned long long removed;
    {
        int lo = lane * 64;
        if (Kb <= lo) removed = ~0ULL;
        else if (Kb >= lo + 64) removed = 0ULL;
        else removed = (~0ULL) << (Kb - lo);
    }

    unsigned long long buf[8];
#pragma unroll
    for (int d = 0; d < 8; d++) buf[d] = (d < Kb) ? g_mask[b][d][lane] : 0ULL;

    for (int ib = 0; ib < PRE; ib += 8) {
        if (ib >= Kb) break;
#pragma unroll
        for (int d = 0; d < 8; d++) {
            int i = ib + d;
            if (i >= Kb) break;             // Kb warp-uniform
            unsigned long long cur = buf[d];
            int pf = i + 8;
            buf[d] = (pf < Kb) ? g_mask[b][pf][lane] : 0ULL;
            unsigned long long rw = __shfl_sync(0xffffffffu, removed, i >> 6);
            if (!((rw >> (i & 63)) & 1ULL)) removed |= cur;
        }
    }

    // compaction: kept bits in ascending slot order -> first POST outputs
    unsigned long long kept = ~removed;
    int cnt = __popcll(kept);
    int incl = cnt;
#pragma unroll
    for (int off = 1; off < 32; off <<= 1) {
        int v = __shfl_up_sync(0xffffffffu, incl, off);
        if (lane >= off) incl += v;
    }
    int base = incl - cnt;

    unsigned long long m = kept;
    while (m) {
        int t = __ffsll(m) - 1;
        m &= m - 1ULL;
        if (base < POST) {
            int slot = lane * 64 + t;
            float* ob = out + ((size_t)b * POST + base) * 4;
            ob[0] = g_by1[b][slot];
            ob[1] = g_bx1[b][slot];
            ob[2] = g_by2[b][slot];
            ob[3] = g_bx2[b][slot];
            out[BATCH * POST * 4 + b * POST + base] = g_sscore[b][slot];
        }
        base++;
    }
}

// ---------------- launch ----------------
extern "C" void kernel_launch(void* const* d_in, const int* in_sizes, int n_in,
                              void* d_out, int out_size) {
    const float* anchor = (const float*)d_in[0];
    const float* breg   = (const float*)d_in[1];
    const float* score  = (const float*)d_in[2];
    float* out = (float*)d_out;

    k_init<<<128, 256>>>(out);
    k_hist<<<dim3(144, BATCH), 256>>>(anchor, breg, score);
    k_thresh<<<1, 32>>>();
    k_gather<<<dim3(576, BATCH), 256>>>(anchor, breg, score);
    k_sort<<<BATCH, 1024>>>();
    k_mask<<<dim3(32, BATCH), 256>>>();
    k_scan<<<BATCH, 32>>>(out);
}

// round 3
// speedup vs baseline: 4.6315x; 4.6315x over previous
#include <cuda_runtime.h>
#include <math.h>

#define BATCH 8
#define NA 147456
#define PRE 2000
#define POST 300
#define NBIN 4096
#define SLOTS 2048
#define NMS_THR 0.7f
#define IMG 1024.0f
#define ABASE 16.0f
#define FULL 0xffffffffu

// ---------------- scratch (zero-initialized at module load; every kernel that
// consumes a buffer restores its zero/overwritten invariant each run) --------
__device__ unsigned int       g_hist[BATCH][NBIN];
__device__ unsigned int       g_valid[BATCH][NA / 32];
__device__ int                g_thresh[BATCH];
__device__ int                g_count[BATCH];
__device__ unsigned long long g_ckey[BATCH][SLOTS];
__device__ float              g_by1[BATCH][SLOTS], g_bx1[BATCH][SLOTS];
__device__ float              g_by2[BATCH][SLOTS], g_bx2[BATCH][SLOTS];
__device__ float              g_sscore[BATCH][SLOTS];
__device__ int                g_K[BATCH];
__device__ unsigned long long g_mask[BATCH][PRE][32];

// ---------------- decode (matches reference bit-for-bit: exp in fp64) -------
__device__ __forceinline__ void decode_box(float4 a, float4 r,
                                           float4& box, bool& valid) {
    float ah  = a.z - a.x;
    float aw  = a.w - a.y;
    float acy = a.x + 0.5f * ah;
    float acx = a.y + 0.5f * aw;
    float cy  = r.x * ah + acy;
    float cx  = r.y * aw + acx;
    float hh  = (float)exp((double)r.z) * ah;
    float ww  = (float)exp((double)r.w) * aw;
    float y1 = fminf(fmaxf(cy - 0.5f * hh, 0.0f), IMG);
    float x1 = fminf(fmaxf(cx - 0.5f * ww, 0.0f), IMG);
    float y2 = fminf(fmaxf(cy + 0.5f * hh, 0.0f), IMG);
    float x2 = fminf(fmaxf(cx + 0.5f * ww, 0.0f), IMG);
    box = make_float4(y1, x1, y2, x2);
    valid = ((y2 - y1) >= ABASE) && ((x2 - x1) >= ABASE);
}

__device__ __forceinline__ int score_bin(float s) {
    int b = (int)(s * 4096.0f);
    return b > 4095 ? 4095 : (b < 0 ? 0 : b);
}

// ---------------- K1: decode + validity bitmap + histogram ----------------
__global__ void k_hist(const float* __restrict__ anchor,
                       const float* __restrict__ reg,
                       const float* __restrict__ score) {
    __shared__ unsigned int sh[NBIN];
    int b = blockIdx.y;
    for (int i = threadIdx.x; i < NBIN; i += 256) sh[i] = 0;
    __syncthreads();
    const float4* A = (const float4*)anchor + (size_t)b * NA;
    const float4* R = (const float4*)reg + (size_t)b * NA;
    const float*  S = score + (size_t)b * NA;
    int base = blockIdx.x * 1024;
    int lane = threadIdx.x & 31;
#pragma unroll
    for (int k = 0; k < 4; k++) {
        int i = base + k * 256 + threadIdx.x;   // 144*1024 == NA exactly
        float4 box; bool valid;
        decode_box(A[i], R[i], box, valid);
        unsigned bal = __ballot_sync(FULL, valid);
        if (lane == 0) g_valid[b][i >> 5] = bal;
        if (valid) atomicAdd(&sh[score_bin(S[i])], 1u);
    }
    __syncthreads();
    for (int i = threadIdx.x; i < NBIN; i += 256)
        if (sh[i]) atomicAdd(&g_hist[b][i], sh[i]);
}

// ---------------- K2: threshold (warp per batch) + out init + hist clear ----
__global__ void k_thresh(float* out) {
    int lane = threadIdx.x & 31;
    int b = threadIdx.x >> 5;                   // 8 warps, one per batch
    unsigned acc = 0;
    for (int s = 127; s >= 0; --s) {
        unsigned v = g_hist[b][s * 32 + lane];
        unsigned r = v;
#pragma unroll
        for (int off = 1; off < 32; off <<= 1) {
            unsigned t = __shfl_down_sync(FULL, r, off);
            if (lane < 32 - off) r += t;        // r = suffix sum within strip
        }
        unsigned tot = __shfl_sync(FULL, r, 0);
        if (acc + tot >= PRE) {
            unsigned bal = __ballot_sync(FULL, acc + r >= PRE);
            if (lane == 0) g_thresh[b] = s * 32 + (31 - __clz(bal));
            break;
        }
        acc += tot;
    }
    __syncthreads();
    // restore hist zero-invariant for next replay
    for (int i = threadIdx.x; i < BATCH * NBIN; i += 256)
        ((unsigned*)g_hist)[i] = 0u;
    // output init: zero boxes+scores, batch indices
    for (int t = threadIdx.x; t < BATCH * POST * 5; t += 256) out[t] = 0.0f;
    for (int t = threadIdx.x; t < BATCH * POST; t += 256)
        out[BATCH * POST * 5 + t] = (float)(t / POST);
}

// ---------------- K3: gather candidate keys (scores + bitmap only) ----------
__global__ void k_gather(const float* __restrict__ score) {
    int b = blockIdx.y;
    int i = blockIdx.x * 256 + threadIdx.x;     // 576*256 == NA exactly
    float s = score[(size_t)b * NA + i];
    int thr = g_thresh[b];
    bool valid = (g_valid[b][i >> 5] >> (i & 31)) & 1u;
    bool cand = valid && (score_bin(s) >= thr);
    unsigned ballot = __ballot_sync(FULL, cand);
    if (cand) {
        int lane = threadIdx.x & 31;
        int leader = __ffs(ballot) - 1;
        int rank = __popc(ballot & ((1u << lane) - 1u));
        int pos = 0;
        if (lane == leader) pos = atomicAdd(&g_count[b], __popc(ballot));
        pos = __shfl_sync(ballot, pos, leader) + rank;
        if (pos < SLOTS) {
            unsigned u = __float_as_uint(s) | 0x80000000u;   // s >= 0
            g_ckey[b][pos] = ((unsigned long long)u << 32) | (unsigned)(~i);
        }
    }
}

// ---------------- K4: keys-only bitonic sort (desc) + decode winners --------
__global__ void k_sort(const float* __restrict__ anchor,
                       const float* __restrict__ reg) {
    __shared__ unsigned long long kk[SLOTS];
    int b = blockIdx.x;
    int tid = threadIdx.x;                       // 1024 threads
    int C = g_count[b];
    if (C > SLOTS) C = SLOTS;
#pragma unroll
    for (int e = 0; e < 2; e++) {
        int i = e * 1024 + tid;
        kk[i] = (i < C) ? g_ckey[b][i] : 0ULL;   // real keys have top bit set
    }
    for (int k = 2; k <= SLOTS; k <<= 1) {
        for (int j = k >> 1; j > 0; j >>= 1) {
            __syncthreads();
#pragma unroll
            for (int e = 0; e < 2; e++) {
                int i = e * 1024 + tid;
                int ixj = i ^ j;
                if (ixj > i) {
                    unsigned long long a = kk[i], c = kk[ixj];
                    bool sw = ((i & k) == 0) ? (a < c) : (a > c);
                    if (sw) { kk[i] = c; kk[ixj] = a; }
                }
            }
        }
    }
    __syncthreads();
    int Kb = (C < PRE) ? C : PRE;
    if (tid == 0) { g_K[b] = Kb; g_count[b] = 0; }  // restore count invariant
    const float4* A = (const float4*)anchor + (size_t)b * NA;
    const float4* R = (const float4*)reg + (size_t)b * NA;
#pragma unroll
    for (int e = 0; e < 2; e++) {
        int p = e * 1024 + tid;
        float4 bx = make_float4(0.f, 0.f, 0.f, 0.f);
        float sc = 0.f;
        if (p < Kb) {
            unsigned long long key = kk[p];
            int i = ~((unsigned)key);            // original anchor index
            bool valid;
            decode_box(A[i], R[i], bx, valid);
            sc = __uint_as_float(((unsigned)(key >> 32)) & 0x7fffffffu);
        }
        g_by1[b][p] = bx.x; g_bx1[b][p] = bx.y;
        g_by2[b][p] = bx.z; g_bx2[b][p] = bx.w;
        g_sscore[b][p] = sc;
    }
}

// ---------------- K5: suppression bitmask (triangular, prefiltered div) -----
__global__ void k_mask() {
    int b = blockIdx.y;
    int bi = blockIdx.x;                         // block of 32 i's (63 blocks)
    int lane = threadIdx.x & 31;
    int warpid = threadIdx.x >> 5;               // 8 warps
    int i = bi * 32 + lane;                      // <= 2015 < SLOTS
    float iy1 = g_by1[b][i], ix1 = g_bx1[b][i];
    float iy2 = g_by2[b][i], ix2 = g_bx2[b][i];
    float ia = (iy2 - iy1) * (ix2 - ix1);
    for (int w = warpid; w < 32; w += 8) {
        if (w * 64 + 63 <= bi * 32) continue;    // whole word is j<=min(i): zero
        unsigned long long bits = 0ULL;
        for (int k = 0; k < 64; k++) {
            int j = w * 64 + k;                  // warp-uniform j
            float jy1 = g_by1[b][j], jx1 = g_bx1[b][j];
            float jy2 = g_by2[b][j], jx2 = g_bx2[b][j];
            float ty = fmaxf(iy1, jy1);
            float by = fminf(iy2, jy2);
            float lx = fmaxf(ix1, jx1);
            float rx = fminf(ix2, jx2);
            float inter = fmaxf(by - ty, 0.f) * fmaxf(rx - lx, 0.f);
            float ja = (jy2 - jy1) * (jx2 - jx1);
            // prefilter: iou>0.7 => 1.7*inter > 0.7*(ia+ja); 2e-4 margin
            if (j > i && inter * 1.7002f > 0.69993f * (ia + ja)) {
                float iou = inter / (ia + ja - inter + 1e-9f);  // exact IEEE
                if (iou > NMS_THR) bits |= (1ULL << k);
            }
        }
        if (i < PRE) g_mask[b][i][w] = bits;
    }
}

// ---------------- K6: greedy scan, 16-i chunks, owner-lane serial chain -----
__global__ void k_scan(float* out) {
    int b = blockIdx.x;
    int lane = threadIdx.x;                      // 32 threads
    int Kb = g_K[b];

    unsigned long long removed;
    {
        int lo = lane * 64;
        if (Kb <= lo) removed = ~0ULL;
        else if (Kb >= lo + 64) removed = 0ULL;
        else removed = (~0ULL) << (Kb - lo);
    }

    unsigned long long cur[16], nxt[16];
#pragma unroll
    for (int d = 0; d < 16; d++) cur[d] = (d < Kb) ? g_mask[b][d][lane] : 0ULL;

    for (int ib = 0; ib < PRE; ib += 16) {
        if (ib >= Kb) break;
#pragma unroll
        for (int d = 0; d < 16; d++) {
            int pf = ib + 16 + d;
            nxt[d] = (pf < Kb) ? g_mask[b][pf][lane] : 0ULL;
        }
        int w = ib >> 6;                         // uniform (16 | 64)
        unsigned dec = 0;
        if (lane == w) {
            unsigned long long rw = removed;
#pragma unroll
            for (int d = 0; d < 16; d++) {
                int i = ib + d;
                if (i < Kb && !((rw >> (i & 63)) & 1ULL)) {
                    dec |= 1u << d;
                    rw |= cur[d];                // cur[d] = mask[i][w] on lane w
                }
            }
        }
        dec = __shfl_sync(FULL, dec, w);
#pragma unroll
        for (int d = 0; d < 16; d++)
            if (dec & (1u << d)) removed |= cur[d];
#pragma unroll
        for (int d = 0; d < 16; d++) cur[d] = nxt[d];
    }

    // compaction: kept bits in ascending slot order -> first POST outputs
    unsigned long long kept = ~removed;
    int cnt = __popcll(kept);
    int incl = cnt;
#pragma unroll
    for (int off = 1; off < 32; off <<= 1) {
        int v = __shfl_up_sync(FULL, incl, off);
        if (lane >= off) incl += v;
    }
    int base = incl - cnt;

    unsigned long long m = kept;
    while (m) {
        int t = __ffsll(m) - 1;
        m &= m - 1ULL;
        if (base < POST) {
            int slot = lane * 64 + t;
            float* ob = out + ((size_t)b * POST + base) * 4;
            ob[0] = g_by1[b][slot];
            ob[1] = g_bx1[b][slot];
            ob[2] = g_by2[b][slot];
            ob[3] = g_bx2[b][slot];
            out[BATCH * POST * 4 + b * POST + base] = g_sscore[b][slot];
        }
        base++;
    }
}

// ---------------- launch ----------------
extern "C" void kernel_launch(void* const* d_in, const int* in_sizes, int n_in,
                              void* d_out, int out_size) {
    const float* anchor = (const float*)d_in[0];
    const float* breg   = (const float*)d_in[1];
    const float* score  = (const float*)d_in[2];
    float* out = (float*)d_out;

    k_hist<<<dim3(144, BATCH), 256>>>(anchor, breg, score);
    k_thresh<<<1, 256>>>(out);
    k_gather<<<dim3(576, BATCH), 256>>>(score);
    k_sort<<<BATCH, 1024>>>(anchor, breg);
    k_mask<<<dim3(63, BATCH), 256>>>();
    k_scan<<<BATCH, 32>>>(out);
}

// round 5
// speedup vs baseline: 4.6854x; 1.0116x over previous
#include <cuda_runtime.h>
#include <math.h>

#define BATCH 8
#define NA 147456
#define PRE 2000
#define POST 300
#define NBIN 4096
#define SLOTS 2048
#define NMS_THR 0.7f
#define IMG 1024.0f
#define ABASE 16.0f
#define FULL 0xffffffffu

// ---------------- scratch (zero-init at load; kernels restore invariants) ---
__device__ unsigned int       g_hist[BATCH][NBIN];
__device__ unsigned int       g_valid[BATCH][NA / 32];
__device__ int                g_thresh[BATCH];
__device__ int                g_count[BATCH];
__device__ unsigned long long g_ckey[BATCH][SLOTS];
__device__ float4             g_box[BATCH][SLOTS];
__device__ float              g_sscore[BATCH][SLOTS];
__device__ int                g_K[BATCH];
__device__ unsigned long long g_mask[BATCH][PRE][32];

// ---------------- exact decode (fp64 exp — reference decision path) ---------
__device__ __forceinline__ void decode_box(float4 a, float4 r,
                                           float4& box, bool& valid) {
    float ah  = a.z - a.x;
    float aw  = a.w - a.y;
    float acy = a.x + 0.5f * ah;
    float acx = a.y + 0.5f * aw;
    float cy  = r.x * ah + acy;
    float cx  = r.y * aw + acx;
    float hh  = (float)exp((double)r.z) * ah;
    float ww  = (float)exp((double)r.w) * aw;
    float y1 = fminf(fmaxf(cy - 0.5f * hh, 0.0f), IMG);
    float x1 = fminf(fmaxf(cx - 0.5f * ww, 0.0f), IMG);
    float y2 = fminf(fmaxf(cy + 0.5f * hh, 0.0f), IMG);
    float x2 = fminf(fmaxf(cx + 0.5f * ww, 0.0f), IMG);
    box = make_float4(y1, x1, y2, x2);
    valid = ((y2 - y1) >= ABASE) && ((x2 - x1) >= ABASE);
}

// fast validity: fp32 __expf with margin; falls back to exact fp64 on boundary
__device__ __forceinline__ bool decode_valid_fast(float4 a, float4 r) {
    float ah  = a.z - a.x;
    float aw  = a.w - a.y;
    float acy = a.x + 0.5f * ah;
    float acx = a.y + 0.5f * aw;
    float cy  = r.x * ah + acy;
    float cx  = r.y * aw + acx;
    float hh  = __expf(r.z) * ah;
    float ww  = __expf(r.w) * aw;
    float y1 = fminf(fmaxf(cy - 0.5f * hh, 0.0f), IMG);
    float x1 = fminf(fmaxf(cx - 0.5f * ww, 0.0f), IMG);
    float y2 = fminf(fmaxf(cy + 0.5f * hh, 0.0f), IMG);
    float x2 = fminf(fmaxf(cx + 0.5f * ww, 0.0f), IMG);
    float dh = (y2 - y1) - ABASE;
    float dw = (x2 - x1) - ABASE;
    float mh = 1e-3f + 1e-5f * fabsf(hh);   // >> worst fast-vs-exact divergence
    float mw = 1e-3f + 1e-5f * fabsf(ww);
    if (fabsf(dh) >= mh && fabsf(dw) >= mw)
        return (dh > 0.0f) && (dw > 0.0f);
    float4 box; bool valid;                 // boundary: exact path
    decode_box(a, r, box, valid);
    return valid;
}

__device__ __forceinline__ int score_bin(float s) {
    int b = (int)(s * 4096.0f);
    return b > 4095 ? 4095 : (b < 0 ? 0 : b);
}

// ---------------- K1: validity bitmap + histogram ----------------
__global__ void k_hist(const float* __restrict__ anchor,
                       const float* __restrict__ reg,
                       const float* __restrict__ score) {
    __shared__ unsigned int sh[NBIN];
    int b = blockIdx.y;
    for (int i = threadIdx.x; i < NBIN; i += 256) sh[i] = 0;
    __syncthreads();
    const float4* A = (const float4*)anchor + (size_t)b * NA;
    const float4* R = (const float4*)reg + (size_t)b * NA;
    const float*  S = score + (size_t)b * NA;
    int base = blockIdx.x * 1024;
    int lane = threadIdx.x & 31;
#pragma unroll
    for (int k = 0; k < 4; k++) {
        int i = base + k * 256 + threadIdx.x;   // 144*1024 == NA exactly
        bool valid = decode_valid_fast(A[i], R[i]);
        unsigned bal = __ballot_sync(FULL, valid);
        if (lane == 0) g_valid[b][i >> 5] = bal;
        if (valid) atomicAdd(&sh[score_bin(S[i])], 1u);
    }
    __syncthreads();
    for (int i = threadIdx.x; i < NBIN; i += 256)
        if (sh[i]) atomicAdd(&g_hist[b][i], sh[i]);
}

// ---------------- K2: threshold (warp/batch) + output init ----------------
__global__ void k_thresh(float* out) {
    int lane = threadIdx.x & 31;
    int b = threadIdx.x >> 5;                   // 8 warps, one per batch
    unsigned acc = 0;
    for (int s = 127; s >= 0; --s) {
        unsigned v = g_hist[b][s * 32 + lane];
        unsigned r = v;
#pragma unroll
        for (int off = 1; off < 32; off <<= 1) {
            unsigned t = __shfl_down_sync(FULL, r, off);
            if (lane < 32 - off) r += t;        // suffix sum within strip
        }
        unsigned tot = __shfl_sync(FULL, r, 0);
        if (acc + tot >= PRE) {
            unsigned bal = __ballot_sync(FULL, acc + r >= PRE);
            if (lane == 0) g_thresh[b] = s * 32 + (31 - __clz(bal));
            break;
        }
        acc += tot;
    }
    // output init: zero boxes+scores, batch indices
    for (int t = threadIdx.x; t < BATCH * POST * 5; t += 256) out[t] = 0.0f;
    for (int t = threadIdx.x; t < BATCH * POST; t += 256)
        out[BATCH * POST * 5 + t] = (float)(t / POST);
}

// ---------------- K3: gather keys + restore hist zero-invariant -------------
__global__ void k_gather(const float* __restrict__ score) {
    int b = blockIdx.y;
    if (blockIdx.x < 16)                        // 16*256 == NBIN
        g_hist[b][blockIdx.x * 256 + threadIdx.x] = 0u;
    int i = blockIdx.x * 256 + threadIdx.x;     // 576*256 == NA exactly
    float s = score[(size_t)b * NA + i];
    int thr = g_thresh[b];
    bool valid = (g_valid[b][i >> 5] >> (i & 31)) & 1u;
    bool cand = valid && (score_bin(s) >= thr);
    unsigned ballot = __ballot_sync(FULL, cand);
    if (cand) {
        int lane = threadIdx.x & 31;
        int leader = __ffs(ballot) - 1;
        int rank = __popc(ballot & ((1u << lane) - 1u));
        int pos = 0;
        if (lane == leader) pos = atomicAdd(&g_count[b], __popc(ballot));
        pos = __shfl_sync(ballot, pos, leader) + rank;
        if (pos < SLOTS) {
            unsigned u = __float_as_uint(s) | 0x80000000u;   // s >= 0
            g_ckey[b][pos] = ((unsigned long long)u << 32) | (unsigned)(~i);
        }
    }
}

// ---------------- K4: hybrid reg/shfl/smem bitonic (desc) + decode winners --
__device__ __forceinline__ void cmpswap(unsigned long long& lo,
                                        unsigned long long& hi, bool takeMax) {
    unsigned long long a = lo, c = hi;
    if (takeMax) { lo = a > c ? a : c; hi = a > c ? c : a; }
    else         { lo = a < c ? a : c; hi = a < c ? c : a; }
}

__global__ void k_sort(const float* __restrict__ anchor,
                       const float* __restrict__ reg) {
    __shared__ unsigned long long sm[SLOTS];
    int b = blockIdx.x;
    int t = threadIdx.x;                        // 512 threads, 4 elems each
    int C = g_count[b];
    if (C > SLOTS) C = SLOTS;
    unsigned long long v[4];
#pragma unroll
    for (int q = 0; q < 4; q++) {
        int e = q * 512 + t;
        v[q] = (e < C) ? g_ckey[b][e] : 0ULL;   // real keys have top bit set
    }
    for (int k = 2; k <= SLOTS; k <<= 1) {
        for (int j = k >> 1; j >= 1; j >>= 1) {
            if (j >= 512) {                     // in-thread exchange
                int jq = j >> 9;
#pragma unroll
                for (int q = 0; q < 4; q++)
                    if (!(q & jq)) {
                        int e = q * 512 + t;
                        cmpswap(v[q], v[q | jq], (e & k) == 0);
                    }
            } else if (j >= 32) {               // cross-warp via smem
                __syncthreads();
#pragma unroll
                for (int q = 0; q < 4; q++) sm[q * 512 + t] = v[q];
                __syncthreads();
#pragma unroll
                for (int q = 0; q < 4; q++) {
                    int e = q * 512 + t;
                    unsigned long long pv = sm[e ^ j];
                    bool takeMax = ((e & k) == 0) ^ ((e & j) != 0);
                    v[q] = takeMax ? (v[q] > pv ? v[q] : pv)
                                   : (v[q] < pv ? v[q] : pv);
                }
            } else {                            // intra-warp via shfl
#pragma unroll
                for (int q = 0; q < 4; q++) {
                    int e = q * 512 + t;
                    unsigned long long pv = __shfl_xor_sync(FULL, v[q], j);
                    bool takeMax = ((e & k) == 0) ^ ((e & j) != 0);
                    v[q] = takeMax ? (v[q] > pv ? v[q] : pv)
                                   : (v[q] < pv ? v[q] : pv);
                }
            }
        }
    }
    int Kb = (C < PRE) ? C : PRE;
    if (t == 0) { g_K[b] = Kb; g_count[b] = 0; }   // restore count invariant
    const float4* A = (const float4*)anchor + (size_t)b * NA;
    const float4* R = (const float4*)reg + (size_t)b * NA;
#pragma unroll
    for (int q = 0; q < 4; q++) {
        int p = q * 512 + t;
        float4 bx = make_float4(0.f, 0.f, 0.f, 0.f);
        float sc = 0.f;
        if (p < Kb) {
            unsigned long long key = v[q];
            int i = ~((unsigned)key);           // original anchor index
            bool valid;
            decode_box(A[i], R[i], bx, valid);  // exact fp64 for winners
            sc = __uint_as_float(((unsigned)(key >> 32)) & 0x7fffffffu);
        }
        g_box[b][p] = bx;
        g_sscore[b][p] = sc;
    }
}

// ---------------- K5: suppression bitmask (triangular, prefiltered div) -----
__global__ void k_mask() {
    int b = blockIdx.y;
    int bi = blockIdx.x;                        // block of 32 i's (63 blocks)
    int lane = threadIdx.x & 31;
    int warpid = threadIdx.x >> 5;              // 8 warps
    int i = bi * 32 + lane;                     // <= 2015 < SLOTS
    float4 ib = g_box[b][i];
    float ia = (ib.z - ib.x) * (ib.w - ib.y);
    for (int w = warpid; w < 32; w += 8) {
        if (w * 64 + 63 <= bi * 32) continue;   // whole word below diagonal
        unsigned long long bits = 0ULL;
        for (int k = 0; k < 64; k++) {
            int j = w * 64 + k;                 // warp-uniform j
            float4 jb = __ldg(&g_box[b][j]);
            float ty = fmaxf(ib.x, jb.x);
            float by = fminf(ib.z, jb.z);
            float lx = fmaxf(ib.y, jb.y);
            float rx = fminf(ib.w, jb.w);
            float inter = fmaxf(by - ty, 0.f) * fmaxf(rx - lx, 0.f);
            float ja = (jb.z - jb.x) * (jb.w - jb.y);
            // prefilter: iou>0.7 => 1.7*inter > 0.7*(ia+ja); 2e-4 margin
            if (j > i && inter * 1.7002f > 0.69993f * (ia + ja)) {
                float iou = inter / (ia + ja - inter + 1e-9f);  // exact IEEE
                if (iou > NMS_THR) bits |= (1ULL << k);
            }
        }
        if (i < PRE) g_mask[b][i][w] = bits;
    }
}

// ---------------- K6: greedy scan, 16-i chunks, owner-lane serial chain -----
__global__ void k_scan(float* out) {
    int b = blockIdx.x;
    int lane = threadIdx.x;                     // 32 threads
    int Kb = g_K[b];

    unsigned long long removed;
    {
        int lo = lane * 64;
        if (Kb <= lo) removed = ~0ULL;
        else if (Kb >= lo + 64) removed = 0ULL;
        else removed = (~0ULL) << (Kb - lo);
    }

    unsigned long long cur[16], nxt[16];
#pragma unroll
    for (int d = 0; d < 16; d++) cur[d] = (d < Kb) ? g_mask[b][d][lane] : 0ULL;

    for (int ib = 0; ib < PRE; ib += 16) {
        if (ib >= Kb) break;
#pragma unroll
        for (int d = 0; d < 16; d++) {
            int pf = ib + 16 + d;
            nxt[d] = (pf < Kb) ? g_mask[b][pf][lane] : 0ULL;
        }
        int w = ib >> 6;                        // uniform (16 | 64)
        unsigned dec = 0;
        if (lane == w) {
            unsigned long long rw = removed;
#pragma unroll
            for (int d = 0; d < 16; d++) {
                int i = ib + d;
                if (i < Kb && !((rw >> (i & 63)) & 1ULL)) {
                    dec |= 1u << d;
                    rw |= cur[d];               // cur[d] = mask[i][w] on lane w
                }
            }
        }
        dec = __shfl_sync(FULL, dec, w);
#pragma unroll
        for (int d = 0; d < 16; d++)
            if (dec & (1u << d)) removed |= cur[d];
#pragma unroll
        for (int d = 0; d < 16; d++) cur[d] = nxt[d];
    }

    // compaction: kept bits in ascending slot order -> first POST outputs
    unsigned long long kept = ~removed;
    int cnt = __popcll(kept);
    int incl = cnt;
#pragma unroll
    for (int off = 1; off < 32; off <<= 1) {
        int v = __shfl_up_sync(FULL, incl, off);
        if (lane >= off) incl += v;
    }
    int base = incl - cnt;

    unsigned long long m = kept;
    while (m) {
        int t = __ffsll(m) - 1;
        m &= m - 1ULL;
        if (base < POST) {
            int slot = lane * 64 + t;
            *(float4*)(out + ((size_t)b * POST + base) * 4) = g_box[b][slot];
            out[BATCH * POST * 4 + b * POST + base] = g_sscore[b][slot];
        }
        base++;
    }
}

// ---------------- launch ----------------
extern "C" void kernel_launch(void* const* d_in, const int* in_sizes, int n_in,
                              void* d_out, int out_size) {
    const float* anchor = (const float*)d_in[0];
    const float* breg   = (const float*)d_in[1];
    const float* score  = (const float*)d_in[2];
    float* out = (float*)d_out;

    k_hist<<<dim3(144, BATCH), 256>>>(anchor, breg, score);
    k_thresh<<<1, 256>>>(out);
    k_gather<<<dim3(576, BATCH), 256>>>(score);
    k_sort<<<BATCH, 512>>>(anchor, breg);
    k_mask<<<dim3(63, BATCH), 256>>>();
    k_scan<<<BATCH, 32>>>(out);
}

// round 6
// speedup vs baseline: 8.2248x; 1.7554x over previous
#include <cuda_runtime.h>
#include <math.h>

#define BATCH 8
#define NA 147456
#define PRE 2000
#define POST 300
#define NBIN 4096
#define SLOTS 2048
#define NMS_THR 0.7f
#define IMG 1024.0f
#define ABASE 16.0f
#define FULL 0xffffffffu

// ---------------- scratch (zero-init at load; kernels restore invariants) ---
__device__ unsigned int       g_hist[BATCH][NBIN];
__device__ unsigned int       g_valid[BATCH][NA / 32];
__device__ int                g_thresh[BATCH];
__device__ int                g_count[BATCH];
__device__ unsigned long long g_ckey[BATCH][SLOTS];
__device__ float4             g_box[BATCH][SLOTS];
__device__ float              g_sscore[BATCH][SLOTS];
__device__ int                g_K[BATCH];
__device__ int                g_done[BATCH];
__device__ unsigned long long g_mask512[BATCH][512][8];
__device__ unsigned long long g_mask[BATCH][PRE][32];

// ---------------- exact decode (fp64 exp — reference decision path) ---------
__device__ __forceinline__ void decode_box(float4 a, float4 r,
                                           float4& box, bool& valid) {
    float ah  = a.z - a.x;
    float aw  = a.w - a.y;
    float acy = a.x + 0.5f * ah;
    float acx = a.y + 0.5f * aw;
    float cy  = r.x * ah + acy;
    float cx  = r.y * aw + acx;
    float hh  = (float)exp((double)r.z) * ah;
    float ww  = (float)exp((double)r.w) * aw;
    float y1 = fminf(fmaxf(cy - 0.5f * hh, 0.0f), IMG);
    float x1 = fminf(fmaxf(cx - 0.5f * ww, 0.0f), IMG);
    float y2 = fminf(fmaxf(cy + 0.5f * hh, 0.0f), IMG);
    float x2 = fminf(fmaxf(cx + 0.5f * ww, 0.0f), IMG);
    box = make_float4(y1, x1, y2, x2);
    valid = ((y2 - y1) >= ABASE) && ((x2 - x1) >= ABASE);
}

// fast validity: fp32 __expf with margin; falls back to exact fp64 on boundary
__device__ __forceinline__ bool decode_valid_fast(float4 a, float4 r) {
    float ah  = a.z - a.x;
    float aw  = a.w - a.y;
    float acy = a.x + 0.5f * ah;
    float acx = a.y + 0.5f * aw;
    float cy  = r.x * ah + acy;
    float cx  = r.y * aw + acx;
    float hh  = __expf(r.z) * ah;
    float ww  = __expf(r.w) * aw;
    float y1 = fminf(fmaxf(cy - 0.5f * hh, 0.0f), IMG);
    float x1 = fminf(fmaxf(cx - 0.5f * ww, 0.0f), IMG);
    float y2 = fminf(fmaxf(cy + 0.5f * hh, 0.0f), IMG);
    float x2 = fminf(fmaxf(cx + 0.5f * ww, 0.0f), IMG);
    float dh = (y2 - y1) - ABASE;
    float dw = (x2 - x1) - ABASE;
    float mh = 1e-3f + 1e-5f * fabsf(hh);   // >> worst fast-vs-exact divergence
    float mw = 1e-3f + 1e-5f * fabsf(ww);
    if (fabsf(dh) >= mh && fabsf(dw) >= mw)
        return (dh > 0.0f) && (dw > 0.0f);
    float4 box; bool valid;                 // boundary: exact path
    decode_box(a, r, box, valid);
    return valid;
}

__device__ __forceinline__ int score_bin(float s) {
    int b = (int)(s * 4096.0f);
    return b > 4095 ? 4095 : (b < 0 ? 0 : b);
}

// ---------------- K1: validity bitmap + histogram ----------------
__global__ void k_hist(const float* __restrict__ anchor,
                       const float* __restrict__ reg,
                       const float* __restrict__ score) {
    __shared__ unsigned int sh[NBIN];
    int b = blockIdx.y;
    for (int i = threadIdx.x; i < NBIN; i += 256) sh[i] = 0;
    __syncthreads();
    const float4* A = (const float4*)anchor + (size_t)b * NA;
    const float4* R = (const float4*)reg + (size_t)b * NA;
    const float*  S = score + (size_t)b * NA;
    int base = blockIdx.x * 1024;
    int lane = threadIdx.x & 31;
#pragma unroll
    for (int k = 0; k < 4; k++) {
        int i = base + k * 256 + threadIdx.x;   // 144*1024 == NA exactly
        bool valid = decode_valid_fast(A[i], R[i]);
        unsigned bal = __ballot_sync(FULL, valid);
        if (lane == 0) g_valid[b][i >> 5] = bal;
        if (valid) atomicAdd(&sh[score_bin(S[i])], 1u);
    }
    __syncthreads();
    for (int i = threadIdx.x; i < NBIN; i += 256)
        if (sh[i]) atomicAdd(&g_hist[b][i], sh[i]);
}

// ---------------- K2: threshold (warp/batch) + output init ----------------
__global__ void k_thresh(float* out) {
    int lane = threadIdx.x & 31;
    int b = threadIdx.x >> 5;                   // 8 warps, one per batch
    unsigned acc = 0;
    for (int s = 127; s >= 0; --s) {
        unsigned v = g_hist[b][s * 32 + lane];
        unsigned r = v;
#pragma unroll
        for (int off = 1; off < 32; off <<= 1) {
            unsigned t = __shfl_down_sync(FULL, r, off);
            if (lane < 32 - off) r += t;        // suffix sum within strip
        }
        unsigned tot = __shfl_sync(FULL, r, 0);
        if (acc + tot >= PRE) {
            unsigned bal = __ballot_sync(FULL, acc + r >= PRE);
            if (lane == 0) g_thresh[b] = s * 32 + (31 - __clz(bal));
            break;
        }
        acc += tot;
    }
    // output init: zero boxes+scores, batch indices
    for (int t = threadIdx.x; t < BATCH * POST * 5; t += 256) out[t] = 0.0f;
    for (int t = threadIdx.x; t < BATCH * POST; t += 256)
        out[BATCH * POST * 5 + t] = (float)(t / POST);
}

// ---------------- K3: gather keys + restore hist zero-invariant -------------
__global__ void k_gather(const float* __restrict__ score) {
    int b = blockIdx.y;
    if (blockIdx.x < 16)                        // 16*256 == NBIN
        g_hist[b][blockIdx.x * 256 + threadIdx.x] = 0u;
    int i = blockIdx.x * 256 + threadIdx.x;     // 576*256 == NA exactly
    float s = score[(size_t)b * NA + i];
    int thr = g_thresh[b];
    bool valid = (g_valid[b][i >> 5] >> (i & 31)) & 1u;
    bool cand = valid && (score_bin(s) >= thr);
    unsigned ballot = __ballot_sync(FULL, cand);
    if (cand) {
        int lane = threadIdx.x & 31;
        int leader = __ffs(ballot) - 1;
        int rank = __popc(ballot & ((1u << lane) - 1u));
        int pos = 0;
        if (lane == leader) pos = atomicAdd(&g_count[b], __popc(ballot));
        pos = __shfl_sync(ballot, pos, leader) + rank;
        if (pos < SLOTS) {
            unsigned u = __float_as_uint(s) | 0x80000000u;   // s >= 0
            g_ckey[b][pos] = ((unsigned long long)u << 32) | (unsigned)(~i);
        }
    }
}

// ---------------- K4: keys-only smem bitonic (desc, 1024 thr) + decode ------
__global__ void k_sort(const float* __restrict__ anchor,
                       const float* __restrict__ reg) {
    __shared__ unsigned long long kk[SLOTS];
    int b = blockIdx.x;
    int tid = threadIdx.x;                       // 1024 threads
    int C = g_count[b];
    if (C > SLOTS) C = SLOTS;
#pragma unroll
    for (int e = 0; e < 2; e++) {
        int i = e * 1024 + tid;
        kk[i] = (i < C) ? g_ckey[b][i] : 0ULL;   // real keys have top bit set
    }
    for (int k = 2; k <= SLOTS; k <<= 1) {
        for (int j = k >> 1; j > 0; j >>= 1) {
            __syncthreads();
#pragma unroll
            for (int e = 0; e < 2; e++) {
                int i = e * 1024 + tid;
                int ixj = i ^ j;
                if (ixj > i) {
                    unsigned long long a = kk[i], c = kk[ixj];
                    bool sw = ((i & k) == 0) ? (a < c) : (a > c);
                    if (sw) { kk[i] = c; kk[ixj] = a; }
                }
            }
        }
    }
    __syncthreads();
    int Kb = (C < PRE) ? C : PRE;
    if (tid == 0) { g_K[b] = Kb; g_count[b] = 0; }  // restore count invariant
    const float4* A = (const float4*)anchor + (size_t)b * NA;
    const float4* R = (const float4*)reg + (size_t)b * NA;
#pragma unroll
    for (int e = 0; e < 2; e++) {
        int p = e * 1024 + tid;
        float4 bx = make_float4(0.f, 0.f, 0.f, 0.f);
        float sc = 0.f;
        if (p < Kb) {
            unsigned long long key = kk[p];
            int i = ~((unsigned)key);            // original anchor index
            bool valid;
            decode_box(A[i], R[i], bx, valid);   // exact fp64 for winners
            sc = __uint_as_float(((unsigned)(key >> 32)) & 0x7fffffffu);
        }
        g_box[b][p] = bx;
        g_sscore[b][p] = sc;
    }
}

// ---------------- shared IoU test ----------------
__device__ __forceinline__ bool iou_over(float4 ib, float ia, float4 jb) {
    float ty = fmaxf(ib.x, jb.x);
    float by = fminf(ib.z, jb.z);
    float lx = fmaxf(ib.y, jb.y);
    float rx = fminf(ib.w, jb.w);
    float inter = fmaxf(by - ty, 0.f) * fmaxf(rx - lx, 0.f);
    float ja = (jb.z - jb.x) * (jb.w - jb.y);
    // prefilter: iou>0.7 => 1.7*inter > 0.7*(ia+ja); 2e-4 margin
    if (inter * 1.7002f > 0.69993f * (ia + ja)) {
        float iou = inter / (ia + ja - inter + 1e-9f);   // exact IEEE
        return iou > NMS_THR;
    }
    return false;
}

// ---------------- K5a: 512-prefix suppression bitmask -----------------------
__global__ void k_mask512() {
    int b = blockIdx.y;
    int bi = blockIdx.x;                        // 16 blocks of 32 i's
    int lane = threadIdx.x & 31;
    int w = threadIdx.x >> 5;                   // 8 warps = words 0..7
    int i = bi * 32 + lane;                     // < 512
    float4 ib = g_box[b][i];
    float ia = (ib.z - ib.x) * (ib.w - ib.y);
    if (w * 64 + 63 <= bi * 32) {               // whole word below diagonal
        g_mask512[b][i][w] = 0ULL;
        return;
    }
    unsigned long long bits = 0ULL;
    for (int k = 0; k < 64; k++) {
        int j = w * 64 + k;                     // warp-uniform j, < 512
        float4 jb = __ldg(&g_box[b][j]);
        if (j > i && iou_over(ib, ia, jb)) bits |= (1ULL << k);
    }
    g_mask512[b][i][w] = bits;
}

// ---------------- K5b: 512-prefix scan; emit output if decisive -------------
__global__ void k_scan512(float* out) {
    int b = blockIdx.x;
    int lane = threadIdx.x;                     // 32 threads; words on lanes<8
    int Kb = g_K[b];
    int K5 = Kb < 512 ? Kb : 512;

    unsigned long long removed;
    if (lane < 8) {
        int lo = lane * 64;
        if (K5 <= lo) removed = ~0ULL;
        else if (K5 >= lo + 64) removed = 0ULL;
        else removed = (~0ULL) << (K5 - lo);
    } else removed = ~0ULL;

    unsigned long long cur[16], nxt[16];
#pragma unroll
    for (int d = 0; d < 16; d++)
        cur[d] = (lane < 8 && d < K5) ? g_mask512[b][d][lane] : 0ULL;

    for (int ib = 0; ib < 512; ib += 16) {
        if (ib >= K5) break;
#pragma unroll
        for (int d = 0; d < 16; d++) {
            int pf = ib + 16 + d;
            nxt[d] = (lane < 8 && pf < K5) ? g_mask512[b][pf][lane] : 0ULL;
        }
        int w = ib >> 6;                        // uniform (16 | 64), < 8
        unsigned dec = 0;
        if (lane == w) {
            unsigned long long rw = removed;
#pragma unroll
            for (int d = 0; d < 16; d++) {
                int i = ib + d;
                if (i < K5 && !((rw >> (i & 63)) & 1ULL)) {
                    dec |= 1u << d;
                    rw |= cur[d];
                }
            }
        }
        dec = __shfl_sync(FULL, dec, w);
#pragma unroll
        for (int d = 0; d < 16; d++)
            if (dec & (1u << d)) removed |= cur[d];
#pragma unroll
        for (int d = 0; d < 16; d++) cur[d] = nxt[d];
    }

    unsigned long long kept = ~removed;         // lanes>=8: 0
    int cnt = __popcll(kept);
    int total = cnt;
#pragma unroll
    for (int off = 16; off >= 1; off >>= 1)
        total += __shfl_xor_sync(FULL, total, off);

    bool done = (total >= POST) || (Kb <= 512); // prefix decides entire output
    if (lane == 0) g_done[b] = done ? 1 : 0;
    if (!done) return;

    int incl = cnt;
#pragma unroll
    for (int off = 1; off < 32; off <<= 1) {
        int v = __shfl_up_sync(FULL, incl, off);
        if (lane >= off) incl += v;
    }
    int base = incl - cnt;

    unsigned long long m = kept;
    while (m) {
        int t = __ffsll(m) - 1;
        m &= m - 1ULL;
        if (base < POST) {
            int slot = lane * 64 + t;           // < 512
            *(float4*)(out + ((size_t)b * POST + base) * 4) = g_box[b][slot];
            out[BATCH * POST * 4 + b * POST + base] = g_sscore[b][slot];
        }
        base++;
    }
}

// ---------------- K6a: full suppression bitmask (fallback, gated) -----------
__global__ void k_mask() {
    int b = blockIdx.y;
    if (g_done[b]) return;                      // prefix path already emitted
    int bi = blockIdx.x;                        // block of 32 i's (63 blocks)
    int lane = threadIdx.x & 31;
    int warpid = threadIdx.x >> 5;              // 8 warps
    int i = bi * 32 + lane;                     // <= 2015 < SLOTS
    float4 ib = g_box[b][i];
    float ia = (ib.z - ib.x) * (ib.w - ib.y);
    for (int w = warpid; w < 32; w += 8) {
        if (w * 64 + 63 <= bi * 32) continue;   // whole word below diagonal
        unsigned long long bits = 0ULL;
        for (int k = 0; k < 64; k++) {
            int j = w * 64 + k;                 // warp-uniform j
            float4 jb = __ldg(&g_box[b][j]);
            if (j > i && iou_over(ib, ia, jb)) bits |= (1ULL << k);
        }
        if (i < PRE) g_mask[b][i][w] = bits;
    }
}

// ---------------- K6b: full greedy scan (fallback, gated) -------------------
__global__ void k_scan(float* out) {
    int b = blockIdx.x;
    if (g_done[b]) return;                      // prefix path already emitted
    int lane = threadIdx.x;                     // 32 threads
    int Kb = g_K[b];

    unsigned long long removed;
    {
        int lo = lane * 64;
        if (Kb <= lo) removed = ~0ULL;
        else if (Kb >= lo + 64) removed = 0ULL;
        else removed = (~0ULL) << (Kb - lo);
    }

    unsigned long long cur[16], nxt[16];
#pragma unroll
    for (int d = 0; d < 16; d++) cur[d] = (d < Kb) ? g_mask[b][d][lane] : 0ULL;

    for (int ib = 0; ib < PRE; ib += 16) {
        if (ib >= Kb) break;
#pragma unroll
        for (int d = 0; d < 16; d++) {
            int pf = ib + 16 + d;
            nxt[d] = (pf < Kb) ? g_mask[b][pf][lane] : 0ULL;
        }
        int w = ib >> 6;                        // uniform (16 | 64)
        unsigned dec = 0;
        if (lane == w) {
            unsigned long long rw = removed;
#pragma unroll
            for (int d = 0; d < 16; d++) {
                int i = ib + d;
                if (i < Kb && !((rw >> (i & 63)) & 1ULL)) {
                    dec |= 1u << d;
                    rw |= cur[d];               // cur[d] = mask[i][w] on lane w
                }
            }
        }
        dec = __shfl_sync(FULL, dec, w);
#pragma unroll
        for (int d = 0; d < 16; d++)
            if (dec & (1u << d)) removed |= cur[d];
#pragma unroll
        for (int d = 0; d < 16; d++) cur[d] = nxt[d];
    }

    // compaction: kept bits in ascending slot order -> first POST outputs
    unsigned long long kept = ~removed;
    int cnt = __popcll(kept);
    int incl = cnt;
#pragma unroll
    for (int off = 1; off < 32; off <<= 1) {
        int v = __shfl_up_sync(FULL, incl, off);
        if (lane >= off) incl += v;
    }
    int base = incl - cnt;

    unsigned long long m = kept;
    while (m) {
        int t = __ffsll(m) - 1;
        m &= m - 1ULL;
        if (base < POST) {
            int slot = lane * 64 + t;
            *(float4*)(out + ((size_t)b * POST + base) * 4) = g_box[b][slot];
            out[BATCH * POST * 4 + b * POST + base] = g_sscore[b][slot];
        }
        base++;
    }
}

// ---------------- launch ----------------
extern "C" void kernel_launch(void* const* d_in, const int* in_sizes, int n_in,
                              void* d_out, int out_size) {
    const float* anchor = (const float*)d_in[0];
    const float* breg   = (const float*)d_in[1];
    const float* score  = (const float*)d_in[2];
    float* out = (float*)d_out;

    k_hist<<<dim3(144, BATCH), 256>>>(anchor, breg, score);
    k_thresh<<<1, 256>>>(out);
    k_gather<<<dim3(576, BATCH), 256>>>(score);
    k_sort<<<BATCH, 1024>>>(anchor, breg);
    k_mask512<<<dim3(16, BATCH), 256>>>();
    k_scan512<<<BATCH, 32>>>(out);
    k_mask<<<dim3(63, BATCH), 256>>>();
    k_scan<<<BATCH, 32>>>(out);
}

// round 7
// speedup vs baseline: 9.3725x; 1.1395x over previous
#include <cuda_runtime.h>
#include <math.h>

#define BATCH 8
#define NA 147456
#define PRE 2000
#define POST 300
#define NBIN 4096
#define SLOTS 2048
#define CAP512 1024
#define NMS_THR 0.7f
#define IMG 1024.0f
#define ABASE 16.0f
#define FULL 0xffffffffu

// ---------------- scratch (zero-init at load; kernels restore invariants) ---
__device__ unsigned int       g_hist[BATCH][NBIN];
__device__ unsigned int       g_valid[BATCH][NA / 32];
__device__ int                g_thr512[BATCH];
__device__ int                g_thresh[BATCH];
__device__ int                g_c512[BATCH];
__device__ int                g_count[BATCH];
__device__ int                g_K[BATCH];      // min(PRE, cnt@thr2000)
__device__ int                g_K512[BATCH];   // raw count @thr512
__device__ int                g_done[BATCH];
__device__ unsigned long long g_key512[BATCH][CAP512];
__device__ unsigned long long g_ckey[BATCH][SLOTS];
__device__ float4             g_box[BATCH][SLOTS];
__device__ float              g_sscore[BATCH][SLOTS];
__device__ unsigned long long g_mask512[BATCH][512][8];
__device__ unsigned long long g_mask[BATCH][PRE][32];

// ---------------- exact decode (fp64 exp — reference decision path) ---------
__device__ __forceinline__ void decode_box(float4 a, float4 r,
                                           float4& box, bool& valid) {
    float ah  = a.z - a.x;
    float aw  = a.w - a.y;
    float acy = a.x + 0.5f * ah;
    float acx = a.y + 0.5f * aw;
    float cy  = r.x * ah + acy;
    float cx  = r.y * aw + acx;
    float hh  = (float)exp((double)r.z) * ah;
    float ww  = (float)exp((double)r.w) * aw;
    float y1 = fminf(fmaxf(cy - 0.5f * hh, 0.0f), IMG);
    float x1 = fminf(fmaxf(cx - 0.5f * ww, 0.0f), IMG);
    float y2 = fminf(fmaxf(cy + 0.5f * hh, 0.0f), IMG);
    float x2 = fminf(fmaxf(cx + 0.5f * ww, 0.0f), IMG);
    box = make_float4(y1, x1, y2, x2);
    valid = ((y2 - y1) >= ABASE) && ((x2 - x1) >= ABASE);
}

// fast validity: fp32 __expf with margin; falls back to exact fp64 on boundary
__device__ __forceinline__ bool decode_valid_fast(float4 a, float4 r) {
    float ah  = a.z - a.x;
    float aw  = a.w - a.y;
    float acy = a.x + 0.5f * ah;
    float acx = a.y + 0.5f * aw;
    float cy  = r.x * ah + acy;
    float cx  = r.y * aw + acx;
    float hh  = __expf(r.z) * ah;
    float ww  = __expf(r.w) * aw;
    float y1 = fminf(fmaxf(cy - 0.5f * hh, 0.0f), IMG);
    float x1 = fminf(fmaxf(cx - 0.5f * ww, 0.0f), IMG);
    float y2 = fminf(fmaxf(cy + 0.5f * hh, 0.0f), IMG);
    float x2 = fminf(fmaxf(cx + 0.5f * ww, 0.0f), IMG);
    float dh = (y2 - y1) - ABASE;
    float dw = (x2 - x1) - ABASE;
    float mh = 1e-3f + 1e-5f * fabsf(hh);   // >> worst fast-vs-exact divergence
    float mw = 1e-3f + 1e-5f * fabsf(ww);
    if (fabsf(dh) >= mh && fabsf(dw) >= mw)
        return (dh > 0.0f) && (dw > 0.0f);
    float4 box; bool valid;                 // boundary: exact path
    decode_box(a, r, box, valid);
    return valid;
}

__device__ __forceinline__ int score_bin(float s) {
    int b = (int)(s * 4096.0f);
    return b > 4095 ? 4095 : (b < 0 ? 0 : b);
}

// ---------------- K1: validity bitmap + histogram (loads batched for MLP) ---
__global__ void k_hist(const float* __restrict__ anchor,
                       const float* __restrict__ reg,
                       const float* __restrict__ score) {
    __shared__ unsigned int sh[NBIN];
    int b = blockIdx.y;
    for (int i = threadIdx.x; i < NBIN; i += 256) sh[i] = 0;
    __syncthreads();
    const float4* A = (const float4*)anchor + (size_t)b * NA;
    const float4* R = (const float4*)reg + (size_t)b * NA;
    const float*  S = score + (size_t)b * NA;
    int base = blockIdx.x * 1024 + threadIdx.x;
    int lane = threadIdx.x & 31;
    float4 a[4], r[4];
    float  s[4];
#pragma unroll
    for (int k = 0; k < 4; k++) {           // all loads issued before any sync
        a[k] = A[base + k * 256];
        r[k] = R[base + k * 256];
        s[k] = S[base + k * 256];
    }
    bool valid[4];
#pragma unroll
    for (int k = 0; k < 4; k++) valid[k] = decode_valid_fast(a[k], r[k]);
#pragma unroll
    for (int k = 0; k < 4; k++) {
        unsigned bal = __ballot_sync(FULL, valid[k]);
        if (lane == 0) g_valid[b][(base + k * 256) >> 5] = bal;
        if (valid[k]) atomicAdd(&sh[score_bin(s[k])], 1u);
    }
    __syncthreads();
    for (int i = threadIdx.x; i < NBIN; i += 256)
        if (sh[i]) atomicAdd(&g_hist[b][i], sh[i]);
}

// ---------------- K2: two thresholds (warp/batch) + output init -------------
__global__ void k_thresh(float* out) {
    int lane = threadIdx.x & 31;
    int b = threadIdx.x >> 5;                   // 8 warps, one per batch
    unsigned acc = 0, cnt2000 = 0;
    int t512 = 0, t2000 = 0;
    bool f512 = false, f2000 = false;
    for (int s = 127; s >= 0 && !f2000; --s) {
        unsigned r = g_hist[b][s * 32 + lane];
#pragma unroll
        for (int off = 1; off < 32; off <<= 1) {
            unsigned t = __shfl_down_sync(FULL, r, off);
            if (lane < 32 - off) r += t;        // suffix sum within strip
        }
        unsigned tot = __shfl_sync(FULL, r, 0);
        if (!f512 && acc + tot >= 512) {
            unsigned bal = __ballot_sync(FULL, acc + r >= 512);
            t512 = s * 32 + (31 - __clz(bal));
            f512 = true;
        }
        if (acc + tot >= PRE) {
            unsigned bal = __ballot_sync(FULL, acc + r >= PRE);
            int L = 31 - __clz(bal);
            t2000 = s * 32 + L;
            cnt2000 = acc + __shfl_sync(FULL, r, L);
            f2000 = true;
        }
        acc += tot;
    }
    if (!f2000) cnt2000 = acc;                  // fewer than PRE valid total
    if (lane == 0) {
        g_thr512[b] = t512;
        g_thresh[b] = t2000;
        g_K[b] = cnt2000 < PRE ? (int)cnt2000 : PRE;
    }
    // output init: zero boxes+scores, batch indices
    for (int t = threadIdx.x; t < BATCH * POST * 5; t += 256) out[t] = 0.0f;
    for (int t = threadIdx.x; t < BATCH * POST; t += 256)
        out[BATCH * POST * 5 + t] = (float)(t / POST);
}

// ---------------- warp-aggregated append ----------------
__device__ __forceinline__ void wappend(bool cand, unsigned long long key,
                                        int* counter,
                                        unsigned long long* buf, int cap,
                                        int lane) {
    unsigned ballot = __ballot_sync(FULL, cand);
    if (cand) {
        int leader = __ffs(ballot) - 1;
        int rank = __popc(ballot & ((1u << lane) - 1u));
        int pos = 0;
        if (lane == leader) pos = atomicAdd(counter, __popc(ballot));
        pos = __shfl_sync(ballot, pos, leader) + rank;
        if (pos < cap) buf[pos] = key;
    }
}

// ---------------- K3: gather both key lists + restore hist invariant --------
__global__ void k_gather(const float* __restrict__ score) {
    int b = blockIdx.y;
    if (blockIdx.x < 16)                        // 16*256 == NBIN
        g_hist[b][blockIdx.x * 256 + threadIdx.x] = 0u;
    int i = blockIdx.x * 256 + threadIdx.x;     // 576*256 == NA exactly
    int lane = threadIdx.x & 31;
    float s = score[(size_t)b * NA + i];
    bool valid = (g_valid[b][i >> 5] >> (i & 31)) & 1u;
    int bin = score_bin(s);
    unsigned u = __float_as_uint(s) | 0x80000000u;   // s >= 0
    unsigned long long key = ((unsigned long long)u << 32) | (unsigned)(~i);
    bool c2000 = valid && (bin >= g_thresh[b]);
    bool c512  = valid && (bin >= g_thr512[b]);      // thr512 >= thr2000
    wappend(c2000, key, &g_count[b], g_ckey[b], SLOTS, lane);
    wappend(c512,  key, &g_c512[b],  g_key512[b], CAP512, lane);
}

// ---------------- K4: 1024-wide bitonic (desc) on top-512 list + decode -----
__global__ void k_sort512(const float* __restrict__ anchor,
                          const float* __restrict__ reg) {
    __shared__ unsigned long long sm[CAP512];
    int b = blockIdx.x;
    int t = threadIdx.x;                        // 512 threads
    int Craw = g_c512[b];
    int C = Craw > CAP512 ? CAP512 : Craw;
    sm[t]       = (t < C)       ? g_key512[b][t]       : 0ULL;
    sm[t + 512] = (t + 512 < C) ? g_key512[b][t + 512] : 0ULL;
    for (int k = 2; k <= CAP512; k <<= 1) {
        for (int j = k >> 1; j > 0; j >>= 1) {
            __syncthreads();
            int i = ((t & ~(j - 1)) << 1) | (t & (j - 1));   // bit j of i == 0
            int p = i | j;
            unsigned long long a = sm[i], c = sm[p];
            bool takeMax = (i & k) == 0;        // descending final order
            if ((a < c) == takeMax) { sm[i] = c; sm[p] = a; }
        }
    }
    __syncthreads();
    if (t == 0) { g_K512[b] = Craw; g_c512[b] = 0; }   // reset invariant
    int K5 = C < 512 ? C : 512;
    const float4* A = (const float4*)anchor + (size_t)b * NA;
    const float4* R = (const float4*)reg + (size_t)b * NA;
    float4 bx = make_float4(0.f, 0.f, 0.f, 0.f);
    float sc = 0.f;
    if (t < K5) {
        unsigned long long key = sm[t];
        int i = ~((unsigned)key);
        bool valid;
        decode_box(A[i], R[i], bx, valid);      // exact fp64 for winners
        sc = __uint_as_float(((unsigned)(key >> 32)) & 0x7fffffffu);
    }
    g_box[b][t] = bx;
    g_sscore[b][t] = sc;
}

// ---------------- shared IoU test ----------------
__device__ __forceinline__ bool iou_over(float4 ib, float ia, float4 jb) {
    float ty = fmaxf(ib.x, jb.x);
    float by = fminf(ib.z, jb.z);
    float lx = fmaxf(ib.y, jb.y);
    float rx = fminf(ib.w, jb.w);
    float inter = fmaxf(by - ty, 0.f) * fmaxf(rx - lx, 0.f);
    float ja = (jb.z - jb.x) * (jb.w - jb.y);
    // prefilter: iou>0.7 => 1.7*inter > 0.7*(ia+ja); 2e-4 margin
    if (inter * 1.7002f > 0.69993f * (ia + ja)) {
        float iou = inter / (ia + ja - inter + 1e-9f);   // exact IEEE
        return iou > NMS_THR;
    }
    return false;
}

// ---------------- K5a: 512-prefix suppression bitmask -----------------------
__global__ void k_mask512() {
    int b = blockIdx.y;
    int bi = blockIdx.x;                        // 16 blocks of 32 i's
    int lane = threadIdx.x & 31;
    int w = threadIdx.x >> 5;                   // 8 warps = words 0..7
    int i = bi * 32 + lane;                     // < 512
    float4 ib = g_box[b][i];
    float ia = (ib.z - ib.x) * (ib.w - ib.y);
    if (w * 64 + 63 <= bi * 32) {               // whole word below diagonal
        g_mask512[b][i][w] = 0ULL;
        return;
    }
    unsigned long long bits = 0ULL;
    for (int k = 0; k < 64; k++) {
        int j = w * 64 + k;                     // warp-uniform j, < 512
        float4 jb = __ldg(&g_box[b][j]);
        if (j > i && iou_over(ib, ia, jb)) bits |= (1ULL << k);
    }
    g_mask512[b][i][w] = bits;
}

// ---------------- K5b: 512-prefix scan; emit output if decisive -------------
__global__ void k_scan512(float* out) {
    int b = blockIdx.x;
    int lane = threadIdx.x;                     // 32 threads; words on lanes<8
    int Kb = g_K[b];
    int Craw = g_K512[b];
    int C = Craw > CAP512 ? CAP512 : Craw;
    int K5 = C < 512 ? C : 512;

    unsigned long long removed;
    if (lane < 8) {
        int lo = lane * 64;
        if (K5 <= lo) removed = ~0ULL;
        else if (K5 >= lo + 64) removed = 0ULL;
        else removed = (~0ULL) << (K5 - lo);
    } else removed = ~0ULL;

    unsigned long long cur[16], nxt[16];
#pragma unroll
    for (int d = 0; d < 16; d++)
        cur[d] = (lane < 8 && d < K5) ? g_mask512[b][d][lane] : 0ULL;

    for (int ib = 0; ib < 512; ib += 16) {
        if (ib >= K5) break;
#pragma unroll
        for (int d = 0; d < 16; d++) {
            int pf = ib + 16 + d;
            nxt[d] = (lane < 8 && pf < K5) ? g_mask512[b][pf][lane] : 0ULL;
        }
        int w = ib >> 6;                        // uniform (16 | 64), < 8
        unsigned dec = 0;
        if (lane == w) {
            unsigned long long rw = removed;
#pragma unroll
            for (int d = 0; d < 16; d++) {
                int i = ib + d;
                if (i < K5 && !((rw >> (i & 63)) & 1ULL)) {
                    dec |= 1u << d;
                    rw |= cur[d];
                }
            }
        }
        dec = __shfl_sync(FULL, dec, w);
#pragma unroll
        for (int d = 0; d < 16; d++)
            if (dec & (1u << d)) removed |= cur[d];
#pragma unroll
        for (int d = 0; d < 16; d++) cur[d] = nxt[d];
    }

    unsigned long long kept = ~removed;         // lanes>=8: 0
    int cnt = __popcll(kept);
    int total = cnt;
#pragma unroll
    for (int off = 16; off >= 1; off >>= 1)
        total += __shfl_xor_sync(FULL, total, off);

    // prefix decides iff it yields >=POST keeps, or it IS the whole list
    bool done = ((total >= POST) || (Kb <= 512)) && (Craw <= CAP512);
    if (lane == 0) g_done[b] = done ? 1 : 0;
    if (!done) return;

    int incl = cnt;
#pragma unroll
    for (int off = 1; off < 32; off <<= 1) {
        int v = __shfl_up_sync(FULL, incl, off);
        if (lane >= off) incl += v;
    }
    int base = incl - cnt;

    unsigned long long m = kept;
    while (m) {
        int t = __ffsll(m) - 1;
        m &= m - 1ULL;
        if (base < POST) {
            int slot = lane * 64 + t;           // < 512
            *(float4*)(out + ((size_t)b * POST + base) * 4) = g_box[b][slot];
            out[BATCH * POST * 4 + b * POST + base] = g_sscore[b][slot];
        }
        base++;
    }
}

// ---------------- K6a: full bitonic sort (fallback, gated) ------------------
__global__ void k_sortF(const float* __restrict__ anchor,
                        const float* __restrict__ reg) {
    __shared__ unsigned long long kk[SLOTS];
    int b = blockIdx.x;
    int tid = threadIdx.x;                       // 1024 threads
    int C = g_count[b];
    __syncthreads();                             // all reads before reset
    if (tid == 0) g_count[b] = 0;                // restore invariant ALWAYS
    if (g_done[b]) return;                       // prefix path already emitted
    if (C > SLOTS) C = SLOTS;
#pragma unroll
    for (int e = 0; e < 2; e++) {
        int i = e * 1024 + tid;
        kk[i] = (i < C) ? g_ckey[b][i] : 0ULL;   // real keys have top bit set
    }
    for (int k = 2; k <= SLOTS; k <<= 1) {
        for (int j = k >> 1; j > 0; j >>= 1) {
            __syncthreads();
#pragma unroll
            for (int e = 0; e < 2; e++) {
                int i = e * 1024 + tid;
                int ixj = i ^ j;
                if (ixj > i) {
                    unsigned long long a = kk[i], c = kk[ixj];
                    bool sw = ((i & k) == 0) ? (a < c) : (a > c);
                    if (sw) { kk[i] = c; kk[ixj] = a; }
                }
            }
        }
    }
    __syncthreads();
    int Kb = (C < PRE) ? C : PRE;
    const float4* A = (const float4*)anchor + (size_t)b * NA;
    const float4* R = (const float4*)reg + (size_t)b * NA;
#pragma unroll
    for (int e = 0; e < 2; e++) {
        int p = e * 1024 + tid;
        float4 bx = make_float4(0.f, 0.f, 0.f, 0.f);
        float sc = 0.f;
        if (p < Kb) {
            unsigned long long key = kk[p];
            int i = ~((unsigned)key);
            bool valid;
            decode_box(A[i], R[i], bx, valid);
            sc = __uint_as_float(((unsigned)(key >> 32)) & 0x7fffffffu);
        }
        g_box[b][p] = bx;
        g_sscore[b][p] = sc;
    }
}

// ---------------- K6b: full suppression bitmask (fallback, gated) -----------
__global__ void k_mask() {
    int b = blockIdx.y;
    if (g_done[b]) return;
    int bi = blockIdx.x;                        // block of 32 i's (63 blocks)
    int lane = threadIdx.x & 31;
    int warpid = threadIdx.x >> 5;              // 8 warps
    int i = bi * 32 + lane;                     // <= 2015 < SLOTS
    float4 ib = g_box[b][i];
    float ia = (ib.z - ib.x) * (ib.w - ib.y);
    for (int w = warpid; w < 32; w += 8) {
        if (w * 64 + 63 <= bi * 32) continue;   // whole word below diagonal
        unsigned long long bits = 0ULL;
        for (int k = 0; k < 64; k++) {
            int j = w * 64 + k;                 // warp-uniform j
            float4 jb = __ldg(&g_box[b][j]);
            if (j > i && iou_over(ib, ia, jb)) bits |= (1ULL << k);
        }
        if (i < PRE) g_mask[b][i][w] = bits;
    }
}

// ---------------- K6c: full greedy scan (fallback, gated) -------------------
__global__ void k_scan(float* out) {
    int b = blockIdx.x;
    if (g_done[b]) return;
    int lane = threadIdx.x;                     // 32 threads
    int Kb = g_K[b];

    unsigned long long removed;
    {
        int lo = lane * 64;
        if (Kb <= lo) removed = ~0ULL;
        else if (Kb >= lo + 64) removed = 0ULL;
        else removed = (~0ULL) << (Kb - lo);
    }

    unsigned long long cur[16], nxt[16];
#pragma unroll
    for (int d = 0; d < 16; d++) cur[d] = (d < Kb) ? g_mask[b][d][lane] : 0ULL;

    for (int ib = 0; ib < PRE; ib += 16) {
        if (ib >= Kb) break;
#pragma unroll
        for (int d = 0; d < 16; d++) {
            int pf = ib + 16 + d;
            nxt[d] = (pf < Kb) ? g_mask[b][pf][lane] : 0ULL;
        }
        int w = ib >> 6;                        // uniform (16 | 64)
        unsigned dec = 0;
        if (lane == w) {
            unsigned long long rw = removed;
#pragma unroll
            for (int d = 0; d < 16; d++) {
                int i = ib + d;
                if (i < Kb && !((rw >> (i & 63)) & 1ULL)) {
                    dec |= 1u << d;
                    rw |= cur[d];
                }
            }
        }
        dec = __shfl_sync(FULL, dec, w);
#pragma unroll
        for (int d = 0; d < 16; d++)
            if (dec & (1u << d)) removed |= cur[d];
#pragma unroll
        for (int d = 0; d < 16; d++) cur[d] = nxt[d];
    }

    unsigned long long kept = ~removed;
    int cnt = __popcll(kept);
    int incl = cnt;
#pragma unroll
    for (int off = 1; off < 32; off <<= 1) {
        int v = __shfl_up_sync(FULL, incl, off);
        if (lane >= off) incl += v;
    }
    int base = incl - cnt;

    unsigned long long m = kept;
    while (m) {
        int t = __ffsll(m) - 1;
        m &= m - 1ULL;
        if (base < POST) {
            int slot = lane * 64 + t;
            *(float4*)(out + ((size_t)b * POST + base) * 4) = g_box[b][slot];
            out[BATCH * POST * 4 + b * POST + base] = g_sscore[b][slot];
        }
        base++;
    }
}

// ---------------- launch ----------------
extern "C" void kernel_launch(void* const* d_in, const int* in_sizes, int n_in,
                              void* d_out, int out_size) {
    const float* anchor = (const float*)d_in[0];
    const float* breg   = (const float*)d_in[1];
    const float* score  = (const float*)d_in[2];
    float* out = (float*)d_out;

    k_hist<<<dim3(144, BATCH), 256>>>(anchor, breg, score);
    k_thresh<<<1, 256>>>(out);
    k_gather<<<dim3(576, BATCH), 256>>>(score);
    k_sort512<<<BATCH, 512>>>(anchor, breg);
    k_mask512<<<dim3(16, BATCH), 256>>>();
    k_scan512<<<BATCH, 32>>>(out);
    k_sortF<<<BATCH, 1024>>>(anchor, breg);
    k_mask<<<dim3(63, BATCH), 256>>>();
    k_scan<<<BATCH, 32>>>(out);
}